// round 16
// baseline (speedup 1.0000x reference)
#include <cuda_runtime.h>
#include <cuda_bf16.h>
#include <math.h>
#include <stdint.h>

#define BB 2
#define SS 2048
#define DD 2048
#define NH 16
#define DH 128
#define RR 64
#define MM (BB*SS)   /* 4096 */

// ---------------- scratch (device globals; no allocation) ----------------
static __device__ float g_wq[DD*RR];
static __device__ float g_wk[DD*RR];
static __device__ float g_wv[DD*RR];
static __device__ float g_wo[DD*RR];
static __device__ float g_resq[4*MM*RR];
static __device__ float g_resk[4*MM*RR];
static __device__ float g_resv[4*MM*RR];
static __device__ float g_ao[(size_t)MM*DD];
static __device__ __nv_bfloat16 g_qhi[(size_t)MM*DD];
static __device__ __nv_bfloat16 g_qlo[(size_t)MM*DD];
static __device__ __nv_bfloat16 g_khi[(size_t)MM*DD];
static __device__ __nv_bfloat16 g_klo[(size_t)MM*DD];
static __device__ __nv_bfloat16 g_vthi[(size_t)MM*DD];  // [b][h][d][s]
static __device__ __nv_bfloat16 g_vtlo[(size_t)MM*DD];

// ---------------- helpers ----------------
__device__ __forceinline__ void mma_bf16(float4& c, const uint32_t* a,
                                         uint32_t b0, uint32_t b1) {
    asm volatile(
        "mma.sync.aligned.m16n8k16.row.col.f32.bf16.bf16.f32 "
        "{%0,%1,%2,%3}, {%4,%5,%6,%7}, {%8,%9}, {%0,%1,%2,%3};\n"
        : "+f"(c.x), "+f"(c.y), "+f"(c.z), "+f"(c.w)
        : "r"(a[0]), "r"(a[1]), "r"(a[2]), "r"(a[3]), "r"(b0), "r"(b1));
}

__device__ __forceinline__ void ldsm_x4(uint32_t& r0, uint32_t& r1,
                                        uint32_t& r2, uint32_t& r3, uint32_t addr) {
    asm volatile("ldmatrix.sync.aligned.m8n8.x4.shared.b16 {%0,%1,%2,%3}, [%4];\n"
                 : "=r"(r0), "=r"(r1), "=r"(r2), "=r"(r3) : "r"(addr));
}

__device__ __forceinline__ void bf16_split2(float v0, float v1,
                                            uint32_t& hi, uint32_t& lo) {
    __nv_bfloat162 h2 = __floats2bfloat162_rn(v0, v1);
    float2 hf = __bfloat1622float2(h2);
    __nv_bfloat162 l2 = __floats2bfloat162_rn(v0 - hf.x, v1 - hf.y);
    hi = *reinterpret_cast<uint32_t*>(&h2);
    lo = *reinterpret_cast<uint32_t*>(&l2);
}

__device__ __forceinline__ void cpa16(uint32_t saddr, const void* gptr) {
    asm volatile("cp.async.cg.shared.global [%0], [%1], 16;\n"
                 :: "r"(saddr), "l"(gptr));
}

// ---------------- w^T = (amp * cos(phase))^T : [64][2048] ------------------
__global__ __launch_bounds__(256) void wcos_t(
        const float* __restrict__ aq, const float* __restrict__ pq, float* __restrict__ wq_,
        const float* __restrict__ ak, const float* __restrict__ pk, float* __restrict__ wk_,
        const float* __restrict__ av, const float* __restrict__ pv, float* __restrict__ wv_,
        const float* __restrict__ ao, const float* __restrict__ po, float* __restrict__ wo_) {
    __shared__ float S[64][68];
    int seg = blockIdx.y;
    const float *a, *p; float* w;
    if (seg == 0)      { a = aq; p = pq; w = wq_; }
    else if (seg == 1) { a = ak; p = pk; w = wk_; }
    else if (seg == 2) { a = av; p = pv; w = wv_; }
    else               { a = ao; p = po; w = wo_; }
    int tid = threadIdx.x;
    int o0 = blockIdx.x * 64;
    #pragma unroll
    for (int it = 0; it < 4; it++) {
        int idx = it*256 + tid;
        int r = idx >> 4, c4 = idx & 15;
        float4 av4 = *reinterpret_cast<const float4*>(&a[(size_t)(o0 + r)*64 + c4*4]);
        float4 pv4 = *reinterpret_cast<const float4*>(&p[(size_t)(o0 + r)*64 + c4*4]);
        S[r][c4*4+0] = av4.x * cosf(pv4.x);
        S[r][c4*4+1] = av4.y * cosf(pv4.y);
        S[r][c4*4+2] = av4.z * cosf(pv4.z);
        S[r][c4*4+3] = av4.w * cosf(pv4.w);
    }
    __syncthreads();
    #pragma unroll
    for (int it = 0; it < 4; it++) {
        int idx = it*256 + tid;
        int hr = idx >> 4, c4 = idx & 15;
        float4 v = make_float4(S[c4*4+0][hr], S[c4*4+1][hr], S[c4*4+2][hr], S[c4*4+3][hr]);
        *reinterpret_cast<float4*>(&w[(size_t)hr*DD + o0 + c4*4]) = v;
    }
}

// ---------------- fused QKV resonance GEMM, k-split x4, TRANSPOSED out ----
__global__ __launch_bounds__(256) void gemm_res_qkv(const float* __restrict__ X,
                                                    const float* __restrict__ BasQ,
                                                    const float* __restrict__ BasK,
                                                    const float* __restrict__ BasV,
                                                    float* __restrict__ outQ,
                                                    float* __restrict__ outK,
                                                    float* __restrict__ outV) {
    __shared__ float SMEM[4*64*36];
    float (*As)[36] = reinterpret_cast<float(*)[36]>(SMEM);
    float (*Bq)[36] = reinterpret_cast<float(*)[36]>(SMEM + 64*36);
    float (*Bk)[36] = reinterpret_cast<float(*)[36]>(SMEM + 2*64*36);
    float (*Bv)[36] = reinterpret_cast<float(*)[36]>(SMEM + 3*64*36);
    int tid = threadIdx.x;
    int tx = tid & 15, ty = tid >> 4;
    int m0 = blockIdx.x * 64;
    int slice = blockIdx.y;
    int k0 = slice * 512, k1 = k0 + 512;

    float aq[4][4] = {}, ak[4][4] = {}, av[4][4] = {};

    for (int kk = k0; kk < k1; kk += 32) {
        #pragma unroll
        for (int t = tid; t < 512; t += 256) {
            int r = t >> 3, c4 = t & 7;
            float4 v = *reinterpret_cast<const float4*>(&X[(size_t)(m0 + r) * DD + kk + c4 * 4]);
            As[r][c4*4+0] = v.x; As[r][c4*4+1] = v.y; As[r][c4*4+2] = v.z; As[r][c4*4+3] = v.w;
            float4 q4 = *reinterpret_cast<const float4*>(&BasQ[(size_t)r * DD + kk + c4 * 4]);
            Bq[r][c4*4+0] = q4.x; Bq[r][c4*4+1] = q4.y; Bq[r][c4*4+2] = q4.z; Bq[r][c4*4+3] = q4.w;
            float4 k4 = *reinterpret_cast<const float4*>(&BasK[(size_t)r * DD + kk + c4 * 4]);
            Bk[r][c4*4+0] = k4.x; Bk[r][c4*4+1] = k4.y; Bk[r][c4*4+2] = k4.z; Bk[r][c4*4+3] = k4.w;
            float4 v4 = *reinterpret_cast<const float4*>(&BasV[(size_t)r * DD + kk + c4 * 4]);
            Bv[r][c4*4+0] = v4.x; Bv[r][c4*4+1] = v4.y; Bv[r][c4*4+2] = v4.z; Bv[r][c4*4+3] = v4.w;
        }
        __syncthreads();
        #pragma unroll
        for (int k = 0; k < 32; k += 4) {
            float4 a[4];
            #pragma unroll
            for (int i = 0; i < 4; i++) a[i] = *reinterpret_cast<const float4*>(&As[ty*4+i][k]);
            float4 b[4];
            #pragma unroll
            for (int j = 0; j < 4; j++) b[j] = *reinterpret_cast<const float4*>(&Bq[tx*4+j][k]);
            #pragma unroll
            for (int i = 0; i < 4; i++)
                #pragma unroll
                for (int j = 0; j < 4; j++)
                    aq[i][j] += a[i].x*b[j].x + a[i].y*b[j].y + a[i].z*b[j].z + a[i].w*b[j].w;
            #pragma unroll
            for (int j = 0; j < 4; j++) b[j] = *reinterpret_cast<const float4*>(&Bk[tx*4+j][k]);
            #pragma unroll
            for (int i = 0; i < 4; i++)
                #pragma unroll
                for (int j = 0; j < 4; j++)
                    ak[i][j] += a[i].x*b[j].x + a[i].y*b[j].y + a[i].z*b[j].z + a[i].w*b[j].w;
            #pragma unroll
            for (int j = 0; j < 4; j++) b[j] = *reinterpret_cast<const float4*>(&Bv[tx*4+j][k]);
            #pragma unroll
            for (int i = 0; i < 4; i++)
                #pragma unroll
                for (int j = 0; j < 4; j++)
                    av[i][j] += a[i].x*b[j].x + a[i].y*b[j].y + a[i].z*b[j].z + a[i].w*b[j].w;
        }
        __syncthreads();
    }

    float (*St)[68] = reinterpret_cast<float(*)[68]>(SMEM);
    float* outs[3] = { outQ, outK, outV };
    for (int oi = 0; oi < 3; oi++) {
        __syncthreads();
        #pragma unroll
        for (int i = 0; i < 4; i++)
            #pragma unroll
            for (int j = 0; j < 4; j++)
                St[tx*4 + j][ty*4 + i] = (oi == 0) ? aq[i][j] : (oi == 1) ? ak[i][j] : av[i][j];
        __syncthreads();
        float* dst = outs[oi];
        #pragma unroll
        for (int it = 0; it < 4; it++) {
            int idx = it*256 + tid;
            int r = idx >> 4, c4 = idx & 15;
            float4 v = *reinterpret_cast<const float4*>(&St[r][c4*4]);
            *reinterpret_cast<float4*>(&dst[(size_t)(slice*64 + r)*MM + m0 + c4*4]) = v;
        }
    }
}

// ---------------- single resonance GEMM, k-split x4, transposed (O proj) ---
__global__ __launch_bounds__(256) void gemm_res(const float* __restrict__ X,
                                                const float* __restrict__ Bas,
                                                float* __restrict__ out) {
    __shared__ float SMEM[2*64*36];
    float (*As)[36] = reinterpret_cast<float(*)[36]>(SMEM);
    float (*Bs)[36] = reinterpret_cast<float(*)[36]>(SMEM + 64*36);
    int tid = threadIdx.x;
    int tx = tid & 15, ty = tid >> 4;
    int m0 = blockIdx.x * 64;
    int slice = blockIdx.y;
    int k0 = slice * 512, k1 = k0 + 512;

    float acc[4][4] = {};

    for (int kk = k0; kk < k1; kk += 32) {
        #pragma unroll
        for (int t = tid; t < 512; t += 256) {
            int r = t >> 3, c4 = t & 7;
            float4 v = *reinterpret_cast<const float4*>(&X[(size_t)(m0 + r) * DD + kk + c4 * 4]);
            As[r][c4*4+0] = v.x; As[r][c4*4+1] = v.y; As[r][c4*4+2] = v.z; As[r][c4*4+3] = v.w;
            float4 b4 = *reinterpret_cast<const float4*>(&Bas[(size_t)r * DD + kk + c4 * 4]);
            Bs[r][c4*4+0] = b4.x; Bs[r][c4*4+1] = b4.y; Bs[r][c4*4+2] = b4.z; Bs[r][c4*4+3] = b4.w;
        }
        __syncthreads();
        #pragma unroll
        for (int k = 0; k < 32; k += 4) {
            float4 a[4], b[4];
            #pragma unroll
            for (int i = 0; i < 4; i++) a[i] = *reinterpret_cast<const float4*>(&As[ty*4+i][k]);
            #pragma unroll
            for (int j = 0; j < 4; j++) b[j] = *reinterpret_cast<const float4*>(&Bs[tx*4+j][k]);
            #pragma unroll
            for (int i = 0; i < 4; i++)
                #pragma unroll
                for (int j = 0; j < 4; j++)
                    acc[i][j] += a[i].x*b[j].x + a[i].y*b[j].y + a[i].z*b[j].z + a[i].w*b[j].w;
        }
        __syncthreads();
    }

    float (*St)[68] = reinterpret_cast<float(*)[68]>(SMEM);
    __syncthreads();
    #pragma unroll
    for (int i = 0; i < 4; i++)
        #pragma unroll
        for (int j = 0; j < 4; j++)
            St[tx*4 + j][ty*4 + i] = acc[i][j];
    __syncthreads();
    #pragma unroll
    for (int it = 0; it < 4; it++) {
        int idx = it*256 + tid;
        int r = idx >> 4, c4 = idx & 15;
        float4 v = *reinterpret_cast<const float4*>(&St[r][c4*4]);
        *reinterpret_cast<float4*>(&out[(size_t)(slice*64 + r)*MM + m0 + c4*4]) = v;
    }
}

// ---------------- expand GEMMs: k-major smem, 128x128 tile, 8x8/thread -----
#define EXP_PITCH 132
#define EXP_SMEM_BYTES (2*64*EXP_PITCH*4)

__device__ __forceinline__ void exp_load_tiles(const float* __restrict__ resT,
                                               const float* __restrict__ wT,
                                               float* As, float* Bs,
                                               int m0, int n0, int tid) {
    #pragma unroll
    for (int it = 0; it < 8; it++) {
        int idx = it*256 + tid;
        int k = idx >> 5, c4 = idx & 31;
        size_t gi = (size_t)k * MM + m0 + c4*4;
        float4 v0 = *reinterpret_cast<const float4*>(&resT[gi]);
        float4 v1 = *reinterpret_cast<const float4*>(&resT[gi + (size_t)64*MM]);
        float4 v2 = *reinterpret_cast<const float4*>(&resT[gi + (size_t)128*MM]);
        float4 v3 = *reinterpret_cast<const float4*>(&resT[gi + (size_t)192*MM]);
        v0.x += v1.x + v2.x + v3.x; v0.y += v1.y + v2.y + v3.y;
        v0.z += v1.z + v2.z + v3.z; v0.w += v1.w + v2.w + v3.w;
        *reinterpret_cast<float4*>(&As[k*EXP_PITCH + c4*4]) = v0;
        float4 wv = *reinterpret_cast<const float4*>(&wT[(size_t)k*DD + n0 + c4*4]);
        *reinterpret_cast<float4*>(&Bs[k*EXP_PITCH + c4*4]) = wv;
    }
}

#define EXP_MAIN(acc) \
    _Pragma("unroll 4") \
    for (int k = 0; k < 64; k++) { \
        float4 a0 = *reinterpret_cast<float4*>(&As[k*EXP_PITCH + ty*4]); \
        float4 a1 = *reinterpret_cast<float4*>(&As[k*EXP_PITCH + 64 + ty*4]); \
        float4 b0 = *reinterpret_cast<float4*>(&Bs[k*EXP_PITCH + tx*4]); \
        float4 b1 = *reinterpret_cast<float4*>(&Bs[k*EXP_PITCH + 64 + tx*4]); \
        float am[2][4] = {{a0.x,a0.y,a0.z,a0.w},{a1.x,a1.y,a1.z,a1.w}}; \
        float bn[2][4] = {{b0.x,b0.y,b0.z,b0.w},{b1.x,b1.y,b1.z,b1.w}}; \
        _Pragma("unroll") for (int mi = 0; mi < 2; mi++) \
        _Pragma("unroll") for (int nj = 0; nj < 2; nj++) \
        _Pragma("unroll") for (int i = 0; i < 4; i++) \
        _Pragma("unroll") for (int j = 0; j < 4; j++) \
            acc[mi][nj][i][j] += am[mi][i] * bn[nj][j]; \
    }

__global__ __launch_bounds__(256) void gemm_expand(const float* __restrict__ resT,
                                                   const float* __restrict__ wT,
                                                   float* __restrict__ out) {
    extern __shared__ float es[];
    float* As = es;
    float* Bs = es + 64*EXP_PITCH;
    int tid = threadIdx.x;
    int tx = tid & 15, ty = tid >> 4;
    int m0 = blockIdx.x * 128, n0 = blockIdx.y * 128;
    exp_load_tiles(resT, wT, As, Bs, m0, n0, tid);
    __syncthreads();
    float acc[2][2][4][4] = {};
    EXP_MAIN(acc)
    #pragma unroll
    for (int mi = 0; mi < 2; mi++)
        #pragma unroll
        for (int i = 0; i < 4; i++) {
            int m = m0 + mi*64 + ty*4 + i;
            #pragma unroll
            for (int nj = 0; nj < 2; nj++) {
                float4 v = make_float4(acc[mi][nj][i][0], acc[mi][nj][i][1],
                                       acc[mi][nj][i][2], acc[mi][nj][i][3]);
                *reinterpret_cast<float4*>(&out[(size_t)m*DD + n0 + nj*64 + tx*4]) = v;
            }
        }
}

__global__ __launch_bounds__(256) void gemm_expand_qk(const float* __restrict__ resT,
                                                      const float* __restrict__ wT,
                                                      __nv_bfloat16* __restrict__ ohi,
                                                      __nv_bfloat16* __restrict__ olo) {
    extern __shared__ float es[];
    float* As = es;
    float* Bs = es + 64*EXP_PITCH;
    int tid = threadIdx.x;
    int tx = tid & 15, ty = tid >> 4;
    int m0 = blockIdx.x * 128, n0 = blockIdx.y * 128;
    exp_load_tiles(resT, wT, As, Bs, m0, n0, tid);
    __syncthreads();
    float acc[2][2][4][4] = {};
    EXP_MAIN(acc)
    #pragma unroll
    for (int mi = 0; mi < 2; mi++)
        #pragma unroll
        for (int i = 0; i < 4; i++) {
            int m = m0 + mi*64 + ty*4 + i;
            #pragma unroll
            for (int nj = 0; nj < 2; nj++) {
                int n = n0 + nj*64 + tx*4;
                uint32_t h0, l0, h1, l1;
                bf16_split2(acc[mi][nj][i][0], acc[mi][nj][i][1], h0, l0);
                bf16_split2(acc[mi][nj][i][2], acc[mi][nj][i][3], h1, l1);
                *reinterpret_cast<uint2*>(&ohi[(size_t)m*DD + n]) = make_uint2(h0, h1);
                *reinterpret_cast<uint2*>(&olo[(size_t)m*DD + n]) = make_uint2(l0, l1);
            }
        }
}

__global__ __launch_bounds__(256) void gemm_expand_vt(const float* __restrict__ resT,
                                                      const float* __restrict__ wT,
                                                      __nv_bfloat16* __restrict__ othi,
                                                      __nv_bfloat16* __restrict__ otlo) {
    extern __shared__ float es[];
    float* As = es;
    float* Bs = es + 64*EXP_PITCH;
    int tid = threadIdx.x;
    int tx = tid & 15, ty = tid >> 4;
    int m0 = blockIdx.x * 128, n0 = blockIdx.y * 128;
    exp_load_tiles(resT, wT, As, Bs, m0, n0, tid);
    __syncthreads();
    float acc[2][2][4][4] = {};
    EXP_MAIN(acc)

    float* St = es;
    int b = m0 >> 11;
    int s0 = m0 & (SS - 1);
    for (int njb = 0; njb < 2; njb++) {
        __syncthreads();
        #pragma unroll
        for (int mi = 0; mi < 2; mi++)
            #pragma unroll
            for (int j = 0; j < 4; j++) {
                float4 v = make_float4(acc[mi][njb][0][j], acc[mi][njb][1][j],
                                       acc[mi][njb][2][j], acc[mi][njb][3][j]);
                *reinterpret_cast<float4*>(&St[(tx*4 + j)*EXP_PITCH + mi*64 + ty*4]) = v;
            }
        __syncthreads();
        #pragma unroll
        for (int it = 0; it < 8; it++) {
            int idx = it*256 + tid;
            int r = idx >> 5, c4 = idx & 31;
            float4 v = *reinterpret_cast<const float4*>(&St[r*EXP_PITCH + c4*4]);
            uint32_t h0, l0, h1, l1;
            bf16_split2(v.x, v.y, h0, l0);
            bf16_split2(v.z, v.w, h1, l1);
            int ng = n0 + njb*64 + r;
            int h = ng >> 7, d = ng & 127;
            size_t base = ((size_t)(b*NH + h)*DH + d)*SS + s0 + c4*4;
            *reinterpret_cast<uint2*>(&othi[base]) = make_uint2(h0, h1);
            *reinterpret_cast<uint2*>(&otlo[base]) = make_uint2(l0, l1);
        }
    }
}

// ---- flash attention: BM=64, 2 CTAs/SM, K dbl-buf + V single-buf pipeline --
#define KP 68
#define VP 36
#define K_HALF 4352                 /* 64*KP */
#define K_BUF  8704                 /* hi+lo */
#define V_HALF 4608                 /* 128*VP */
#define OFF_V  17408                /* after 2 K bufs */
#define ATTN_SMEM_U32 (OFF_V + 2*V_HALF)   /* 26624 */
#define ATTN_SMEM_BYTES (ATTN_SMEM_U32 * 4)   /* 106496 */

__global__ __launch_bounds__(128, 2) void attn_kernel() {
    extern __shared__ uint32_t smu[];
    uint32_t sbase = (uint32_t)__cvta_generic_to_shared(smu);

    int tid = threadIdx.x;
    int wid = tid >> 5, lane = tid & 31;
    int g = lane >> 2, t4 = lane & 3;
    int qt = blockIdx.x, h = blockIdx.y, bz = blockIdx.z;
    const float scale = 0.08838834764831845f;
    int m0w = wid * 16;   // wid 0..3 -> rows 0..63

    size_t vtoff = ((size_t)(bz*NH + h) * DH) * SS;

    // ldmatrix lane->row offsets (u32 units, within tile)
    int k_lm = ((lane>>4)*8 + (lane&7)) * KP + ((lane>>3)&1)*4;
    int v_lm = ((lane>>4)*8 + (lane&7)) * VP + ((lane>>3)&1)*4;

    // ---- prologue: issue K(0) into buf 0 ----
    {
        size_t koff = (size_t)(bz*SS)*DD + h*DH;
        const uint4* kh4 = reinterpret_cast<const uint4*>(g_khi + koff);
        const uint4* kl4 = reinterpret_cast<const uint4*>(g_klo + koff);
        uint32_t kh_s = sbase, kl_s = sbase + K_HALF*4;
        for (int t = tid; t < 1024; t += 128) {
            int kr = t >> 4, kc = t & 15;
            cpa16(kh_s + (kr*KP + kc*4)*4, kh4 + (size_t)kr*256 + kc);
            cpa16(kl_s + (kr*KP + kc*4)*4, kl4 + (size_t)kr*256 + kc);
        }
        asm volatile("cp.async.commit_group;\n");
    }

    // ---- Q fragments into registers (once) ----
    size_t qrow0 = (size_t)(bz*SS + qt*64 + m0w + g)*DD + h*DH;
    const uint32_t* qh0 = reinterpret_cast<const uint32_t*>(g_qhi + qrow0);
    const uint32_t* qh8 = reinterpret_cast<const uint32_t*>(g_qhi + qrow0 + (size_t)8*DD);
    const uint32_t* ql0 = reinterpret_cast<const uint32_t*>(g_qlo + qrow0);
    const uint32_t* ql8 = reinterpret_cast<const uint32_t*>(g_qlo + qrow0 + (size_t)8*DD);
    uint32_t qa_h[8][4], qa_l[8][4];
    #pragma unroll
    for (int ks = 0; ks < 8; ks++) {
        int c = ks*8 + t4;
        qa_h[ks][0] = qh0[c];   qa_h[ks][1] = qh8[c];
        qa_h[ks][2] = qh0[c+4]; qa_h[ks][3] = qh8[c+4];
        qa_l[ks][0] = ql0[c];   qa_l[ks][1] = ql8[c];
        qa_l[ks][2] = ql0[c+4]; qa_l[ks][3] = ql8[c+4];
    }

    float4 oacc[16];
    #pragma unroll
    for (int i = 0; i < 16; i++) oacc[i] = make_float4(0.f,0.f,0.f,0.f);
    float mr0 = -INFINITY, mr1 = -INFINITY, lr0 = 0.f, lr1 = 0.f;

    for (int jt = 0; jt < 32; jt++) {
        __syncthreads();   // PV(jt-1) done by all warps: V buffer reusable, K buf (jt+1)&1 reusable

        // ---- issue V(jt) into the single V buffer ----
        {
            const uint4* vh4 = reinterpret_cast<const uint4*>(g_vthi + vtoff + jt*64);
            const uint4* vl4 = reinterpret_cast<const uint4*>(g_vtlo + vtoff + jt*64);
            uint32_t vh_s = sbase + OFF_V*4, vl_s = vh_s + V_HALF*4;
            for (int t = tid; t < 1024; t += 128) {
                int vr = t >> 3, vc = t & 7;
                cpa16(vh_s + (vr*VP + vc*4)*4, vh4 + (size_t)vr*256 + vc);
                cpa16(vl_s + (vr*VP + vc*4)*4, vl4 + (size_t)vr*256 + vc);
            }
            asm volatile("cp.async.commit_group;\n");
        }
        // ---- issue K(jt+1) into buf (jt+1)&1 (empty group on last iter) ----
        if (jt + 1 < 32) {
            int nb = (jt + 1) & 1;
            size_t koff = (size_t)(bz*SS + (jt+1)*64)*DD + h*DH;
            const uint4* kh4 = reinterpret_cast<const uint4*>(g_khi + koff);
            const uint4* kl4 = reinterpret_cast<const uint4*>(g_klo + koff);
            uint32_t kh_s = sbase + nb*K_BUF*4, kl_s = kh_s + K_HALF*4;
            for (int t = tid; t < 1024; t += 128) {
                int kr = t >> 4, kc = t & 15;
                cpa16(kh_s + (kr*KP + kc*4)*4, kh4 + (size_t)kr*256 + kc);
                cpa16(kl_s + (kr*KP + kc*4)*4, kl4 + (size_t)kr*256 + kc);
            }
        }
        asm volatile("cp.async.commit_group;\n");

        // ---- wait K(jt): pending {K(jt), V(jt), K(jt+1)} -> keep newest 2 ----
        asm volatile("cp.async.wait_group 2;\n" ::: "memory");
        __syncthreads();

        int buf = jt & 1;
        uint32_t kh_base = sbase + (buf*K_BUF + k_lm)*4;
        uint32_t kl_base = kh_base + K_HALF*4;

        // ---- S = Q @ K^T ----
        float4 sc[8];
        #pragma unroll
        for (int i = 0; i < 8; i++) sc[i] = make_float4(0.f,0.f,0.f,0.f);
        #pragma unroll
        for (int ks = 0; ks < 8; ks++) {
            #pragma unroll
            for (int nb = 0; nb < 8; nb += 2) {
                uint32_t h0, h1, h2, h3, l0, l1, l2, l3;
                ldsm_x4(h0, h1, h2, h3, kh_base + (nb*8*KP + ks*8)*4);
                ldsm_x4(l0, l1, l2, l3, kl_base + (nb*8*KP + ks*8)*4);
                mma_bf16(sc[nb],   qa_h[ks], h0, h1);
                mma_bf16(sc[nb],   qa_h[ks], l0, l1);
                mma_bf16(sc[nb],   qa_l[ks], h0, h1);
                mma_bf16(sc[nb+1], qa_h[ks], h2, h3);
                mma_bf16(sc[nb+1], qa_h[ks], l2, l3);
                mma_bf16(sc[nb+1], qa_l[ks], h2, h3);
            }
        }

        // ---- wait V(jt): pending {V(jt), K(jt+1)} -> keep newest 1 ----
        asm volatile("cp.async.wait_group 1;\n" ::: "memory");
        __syncthreads();

        uint32_t vh_base = sbase + (OFF_V + v_lm)*4;
        uint32_t vl_base = vh_base + V_HALF*4;

        // ---- online softmax ----
        float mx0 = -INFINITY, mx1 = -INFINITY;
        #pragma unroll
        for (int nt = 0; nt < 8; nt++) {
            mx0 = fmaxf(mx0, fmaxf(sc[nt].x, sc[nt].y));
            mx1 = fmaxf(mx1, fmaxf(sc[nt].z, sc[nt].w));
        }
        mx0 *= scale; mx1 *= scale;
        mx0 = fmaxf(mx0, __shfl_xor_sync(0xffffffffu, mx0, 1));
        mx0 = fmaxf(mx0, __shfl_xor_sync(0xffffffffu, mx0, 2));
        mx1 = fmaxf(mx1, __shfl_xor_sync(0xffffffffu, mx1, 1));
        mx1 = fmaxf(mx1, __shfl_xor_sync(0xffffffffu, mx1, 2));
        float mn0 = fmaxf(mr0, mx0), mn1 = fmaxf(mr1, mx1);
        float ps0 = 0.f, ps1 = 0.f;
        #pragma unroll
        for (int nt = 0; nt < 8; nt++) {
            sc[nt].x = __expf(sc[nt].x*scale - mn0);
            sc[nt].y = __expf(sc[nt].y*scale - mn0);
            sc[nt].z = __expf(sc[nt].z*scale - mn1);
            sc[nt].w = __expf(sc[nt].w*scale - mn1);
            ps0 += sc[nt].x + sc[nt].y;
            ps1 += sc[nt].z + sc[nt].w;
        }
        ps0 += __shfl_xor_sync(0xffffffffu, ps0, 1);
        ps0 += __shfl_xor_sync(0xffffffffu, ps0, 2);
        ps1 += __shfl_xor_sync(0xffffffffu, ps1, 1);
        ps1 += __shfl_xor_sync(0xffffffffu, ps1, 2);
        float al0 = __expf(mr0 - mn0), al1 = __expf(mr1 - mn1);
        lr0 = lr0*al0 + ps0; lr1 = lr1*al1 + ps1;
        mr0 = mn0; mr1 = mn1;
        #pragma unroll
        for (int i = 0; i < 16; i++) {
            oacc[i].x *= al0; oacc[i].y *= al0;
            oacc[i].z *= al1; oacc[i].w *= al1;
        }

        // ---- O += P @ V : P A-fragments from sc registers ----
        #pragma unroll
        for (int ks = 0; ks < 4; ks++) {
            uint32_t ah[4], al[4];
            bf16_split2(sc[2*ks].x,   sc[2*ks].y,   ah[0], al[0]);
            bf16_split2(sc[2*ks].z,   sc[2*ks].w,   ah[1], al[1]);
            bf16_split2(sc[2*ks+1].x, sc[2*ks+1].y, ah[2], al[2]);
            bf16_split2(sc[2*ks+1].z, sc[2*ks+1].w, ah[3], al[3]);
            #pragma unroll
            for (int nb = 0; nb < 16; nb += 2) {
                uint32_t h0, h1, h2, h3, l0, l1, l2, l3;
                ldsm_x4(h0, h1, h2, h3, vh_base + (nb*8*VP + ks*8)*4);
                ldsm_x4(l0, l1, l2, l3, vl_base + (nb*8*VP + ks*8)*4);
                mma_bf16(oacc[nb],   ah, h0, h1);
                mma_bf16(oacc[nb],   ah, l0, l1);
                mma_bf16(oacc[nb],   al, h0, h1);
                mma_bf16(oacc[nb+1], ah, h2, h3);
                mma_bf16(oacc[nb+1], ah, l2, l3);
                mma_bf16(oacc[nb+1], al, h2, h3);
            }
        }
    }

    // ---- epilogue ----
    float inv0 = 1.f/lr0, inv1 = 1.f/lr1;
    size_t row0 = (size_t)(bz*SS + qt*64 + m0w + g);
    float* ob0 = g_ao + row0*DD + h*DH;
    float* ob1 = ob0 + (size_t)8*DD;
    #pragma unroll
    for (int nt = 0; nt < 16; nt++) {
        int c = nt*8 + 2*t4;
        *reinterpret_cast<float2*>(&ob0[c]) = make_float2(oacc[nt].x*inv0, oacc[nt].y*inv0);
        *reinterpret_cast<float2*>(&ob1[c]) = make_float2(oacc[nt].z*inv1, oacc[nt].w*inv1);
    }
}

// ---------------- launch ----------------
extern "C" void kernel_launch(void* const* d_in, const int* in_sizes, int n_in,
                              void* d_out, int out_size) {
    const float* x       = (const float*)d_in[0];
    const float* basis_q = (const float*)d_in[1];
    const float* phase_q = (const float*)d_in[2];
    const float* amp_q   = (const float*)d_in[3];
    const float* basis_k = (const float*)d_in[4];
    const float* phase_k = (const float*)d_in[5];
    const float* amp_k   = (const float*)d_in[6];
    const float* basis_v = (const float*)d_in[7];
    const float* phase_v = (const float*)d_in[8];
    const float* amp_v   = (const float*)d_in[9];
    const float* basis_o = (const float*)d_in[10];
    const float* phase_o = (const float*)d_in[11];
    const float* amp_o   = (const float*)d_in[12];
    float* out = (float*)d_out;

    float *wq, *wk, *wv, *wo, *resq, *resk, *resv, *ao;
    __nv_bfloat16 *qhi, *qlo, *khi, *klo, *vthi, *vtlo;
    cudaGetSymbolAddress((void**)&wq, g_wq);
    cudaGetSymbolAddress((void**)&wk, g_wk);
    cudaGetSymbolAddress((void**)&wv, g_wv);
    cudaGetSymbolAddress((void**)&wo, g_wo);
    cudaGetSymbolAddress((void**)&resq, g_resq);
    cudaGetSymbolAddress((void**)&resk, g_resk);
    cudaGetSymbolAddress((void**)&resv, g_resv);
    cudaGetSymbolAddress((void**)&ao, g_ao);
    cudaGetSymbolAddress((void**)&qhi, g_qhi);
    cudaGetSymbolAddress((void**)&qlo, g_qlo);
    cudaGetSymbolAddress((void**)&khi, g_khi);
    cudaGetSymbolAddress((void**)&klo, g_klo);
    cudaGetSymbolAddress((void**)&vthi, g_vthi);
    cudaGetSymbolAddress((void**)&vtlo, g_vtlo);

    cudaFuncSetAttribute(attn_kernel, cudaFuncAttributeMaxDynamicSharedMemorySize,
                         ATTN_SMEM_BYTES);
    cudaFuncSetAttribute(gemm_expand, cudaFuncAttributeMaxDynamicSharedMemorySize,
                         EXP_SMEM_BYTES);
    cudaFuncSetAttribute(gemm_expand_qk, cudaFuncAttributeMaxDynamicSharedMemorySize,
                         EXP_SMEM_BYTES);
    cudaFuncSetAttribute(gemm_expand_vt, cudaFuncAttributeMaxDynamicSharedMemorySize,
                         EXP_SMEM_BYTES);

    wcos_t<<<dim3(32, 4), 256>>>(amp_q, phase_q, wq, amp_k, phase_k, wk,
                                 amp_v, phase_v, wv, amp_o, phase_o, wo);

    gemm_res_qkv<<<dim3(64, 4), 256>>>(x, basis_q, basis_k, basis_v, resq, resk, resv);
    gemm_expand_qk<<<dim3(32, 16), 256, EXP_SMEM_BYTES>>>(resq, wq, qhi, qlo);
    gemm_expand_qk<<<dim3(32, 16), 256, EXP_SMEM_BYTES>>>(resk, wk, khi, klo);
    gemm_expand_vt<<<dim3(32, 16), 256, EXP_SMEM_BYTES>>>(resv, wv, vthi, vtlo);

    // BM=64: 32 q-tiles, 128 threads, 2 CTAs/SM
    attn_kernel<<<dim3(32, NH, BB), 128, ATTN_SMEM_BYTES>>>();

    gemm_res<<<dim3(64, 4), 256>>>(ao, basis_o, resq);
    gemm_expand<<<dim3(32, 16), 256, EXP_SMEM_BYTES>>>(resq, wo, out);
}

// round 17
// speedup vs baseline: 1.5638x; 1.5638x over previous
#include <cuda_runtime.h>
#include <cuda_bf16.h>
#include <math.h>
#include <stdint.h>

#define BB 2
#define SS 2048
#define DD 2048
#define NH 16
#define DH 128
#define RR 64
#define MM (BB*SS)   /* 4096 */

// ---------------- scratch (device globals; no allocation) ----------------
static __device__ float g_wq[DD*RR];
static __device__ float g_wk[DD*RR];
static __device__ float g_wv[DD*RR];
static __device__ float g_wo[DD*RR];
static __device__ float g_resq[4*MM*RR];
static __device__ float g_resk[4*MM*RR];
static __device__ float g_resv[4*MM*RR];
static __device__ float g_ao[(size_t)MM*DD];
static __device__ __nv_bfloat16 g_qhi[(size_t)MM*DD];
static __device__ __nv_bfloat16 g_qlo[(size_t)MM*DD];
static __device__ __nv_bfloat16 g_khi[(size_t)MM*DD];
static __device__ __nv_bfloat16 g_klo[(size_t)MM*DD];
static __device__ __nv_bfloat16 g_vthi[(size_t)MM*DD];  // [b][h][d][s]
static __device__ __nv_bfloat16 g_vtlo[(size_t)MM*DD];

// ---------------- helpers ----------------
__device__ __forceinline__ void mma_bf16(float4& c, const uint32_t* a,
                                         uint32_t b0, uint32_t b1) {
    asm volatile(
        "mma.sync.aligned.m16n8k16.row.col.f32.bf16.bf16.f32 "
        "{%0,%1,%2,%3}, {%4,%5,%6,%7}, {%8,%9}, {%0,%1,%2,%3};\n"
        : "+f"(c.x), "+f"(c.y), "+f"(c.z), "+f"(c.w)
        : "r"(a[0]), "r"(a[1]), "r"(a[2]), "r"(a[3]), "r"(b0), "r"(b1));
}

__device__ __forceinline__ void ldsm_x4(uint32_t& r0, uint32_t& r1,
                                        uint32_t& r2, uint32_t& r3, uint32_t addr) {
    asm volatile("ldmatrix.sync.aligned.m8n8.x4.shared.b16 {%0,%1,%2,%3}, [%4];\n"
                 : "=r"(r0), "=r"(r1), "=r"(r2), "=r"(r3) : "r"(addr));
}

__device__ __forceinline__ void bf16_split2(float v0, float v1,
                                            uint32_t& hi, uint32_t& lo) {
    __nv_bfloat162 h2 = __floats2bfloat162_rn(v0, v1);
    float2 hf = __bfloat1622float2(h2);
    __nv_bfloat162 l2 = __floats2bfloat162_rn(v0 - hf.x, v1 - hf.y);
    hi = *reinterpret_cast<uint32_t*>(&h2);
    lo = *reinterpret_cast<uint32_t*>(&l2);
}

__device__ __forceinline__ void cpa16(uint32_t saddr, const void* gptr) {
    asm volatile("cp.async.cg.shared.global [%0], [%1], 16;\n"
                 :: "r"(saddr), "l"(gptr));
}

// ---------------- w^T = (amp * cos(phase))^T : [64][2048] ------------------
__global__ __launch_bounds__(256) void wcos_t(
        const float* __restrict__ aq, const float* __restrict__ pq, float* __restrict__ wq_,
        const float* __restrict__ ak, const float* __restrict__ pk, float* __restrict__ wk_,
        const float* __restrict__ av, const float* __restrict__ pv, float* __restrict__ wv_,
        const float* __restrict__ ao, const float* __restrict__ po, float* __restrict__ wo_) {
    __shared__ float S[64][68];
    int seg = blockIdx.y;
    const float *a, *p; float* w;
    if (seg == 0)      { a = aq; p = pq; w = wq_; }
    else if (seg == 1) { a = ak; p = pk; w = wk_; }
    else if (seg == 2) { a = av; p = pv; w = wv_; }
    else               { a = ao; p = po; w = wo_; }
    int tid = threadIdx.x;
    int o0 = blockIdx.x * 64;
    #pragma unroll
    for (int it = 0; it < 4; it++) {
        int idx = it*256 + tid;
        int r = idx >> 4, c4 = idx & 15;
        float4 av4 = *reinterpret_cast<const float4*>(&a[(size_t)(o0 + r)*64 + c4*4]);
        float4 pv4 = *reinterpret_cast<const float4*>(&p[(size_t)(o0 + r)*64 + c4*4]);
        S[r][c4*4+0] = av4.x * cosf(pv4.x);
        S[r][c4*4+1] = av4.y * cosf(pv4.y);
        S[r][c4*4+2] = av4.z * cosf(pv4.z);
        S[r][c4*4+3] = av4.w * cosf(pv4.w);
    }
    __syncthreads();
    #pragma unroll
    for (int it = 0; it < 4; it++) {
        int idx = it*256 + tid;
        int hr = idx >> 4, c4 = idx & 15;
        float4 v = make_float4(S[c4*4+0][hr], S[c4*4+1][hr], S[c4*4+2][hr], S[c4*4+3][hr]);
        *reinterpret_cast<float4*>(&w[(size_t)hr*DD + o0 + c4*4]) = v;
    }
}

// ---------------- fused QKV resonance GEMM, k-split x4, TRANSPOSED out ----
__global__ __launch_bounds__(256) void gemm_res_qkv(const float* __restrict__ X,
                                                    const float* __restrict__ BasQ,
                                                    const float* __restrict__ BasK,
                                                    const float* __restrict__ BasV,
                                                    float* __restrict__ outQ,
                                                    float* __restrict__ outK,
                                                    float* __restrict__ outV) {
    __shared__ float SMEM[4*64*36];
    float (*As)[36] = reinterpret_cast<float(*)[36]>(SMEM);
    float (*Bq)[36] = reinterpret_cast<float(*)[36]>(SMEM + 64*36);
    float (*Bk)[36] = reinterpret_cast<float(*)[36]>(SMEM + 2*64*36);
    float (*Bv)[36] = reinterpret_cast<float(*)[36]>(SMEM + 3*64*36);
    int tid = threadIdx.x;
    int tx = tid & 15, ty = tid >> 4;
    int m0 = blockIdx.x * 64;
    int slice = blockIdx.y;
    int k0 = slice * 512, k1 = k0 + 512;

    float aq[4][4] = {}, ak[4][4] = {}, av[4][4] = {};

    for (int kk = k0; kk < k1; kk += 32) {
        #pragma unroll
        for (int t = tid; t < 512; t += 256) {
            int r = t >> 3, c4 = t & 7;
            float4 v = *reinterpret_cast<const float4*>(&X[(size_t)(m0 + r) * DD + kk + c4 * 4]);
            As[r][c4*4+0] = v.x; As[r][c4*4+1] = v.y; As[r][c4*4+2] = v.z; As[r][c4*4+3] = v.w;
            float4 q4 = *reinterpret_cast<const float4*>(&BasQ[(size_t)r * DD + kk + c4 * 4]);
            Bq[r][c4*4+0] = q4.x; Bq[r][c4*4+1] = q4.y; Bq[r][c4*4+2] = q4.z; Bq[r][c4*4+3] = q4.w;
            float4 k4 = *reinterpret_cast<const float4*>(&BasK[(size_t)r * DD + kk + c4 * 4]);
            Bk[r][c4*4+0] = k4.x; Bk[r][c4*4+1] = k4.y; Bk[r][c4*4+2] = k4.z; Bk[r][c4*4+3] = k4.w;
            float4 v4 = *reinterpret_cast<const float4*>(&BasV[(size_t)r * DD + kk + c4 * 4]);
            Bv[r][c4*4+0] = v4.x; Bv[r][c4*4+1] = v4.y; Bv[r][c4*4+2] = v4.z; Bv[r][c4*4+3] = v4.w;
        }
        __syncthreads();
        #pragma unroll
        for (int k = 0; k < 32; k += 4) {
            float4 a[4];
            #pragma unroll
            for (int i = 0; i < 4; i++) a[i] = *reinterpret_cast<const float4*>(&As[ty*4+i][k]);
            float4 b[4];
            #pragma unroll
            for (int j = 0; j < 4; j++) b[j] = *reinterpret_cast<const float4*>(&Bq[tx*4+j][k]);
            #pragma unroll
            for (int i = 0; i < 4; i++)
                #pragma unroll
                for (int j = 0; j < 4; j++)
                    aq[i][j] += a[i].x*b[j].x + a[i].y*b[j].y + a[i].z*b[j].z + a[i].w*b[j].w;
            #pragma unroll
            for (int j = 0; j < 4; j++) b[j] = *reinterpret_cast<const float4*>(&Bk[tx*4+j][k]);
            #pragma unroll
            for (int i = 0; i < 4; i++)
                #pragma unroll
                for (int j = 0; j < 4; j++)
                    ak[i][j] += a[i].x*b[j].x + a[i].y*b[j].y + a[i].z*b[j].z + a[i].w*b[j].w;
            #pragma unroll
            for (int j = 0; j < 4; j++) b[j] = *reinterpret_cast<const float4*>(&Bv[tx*4+j][k]);
            #pragma unroll
            for (int i = 0; i < 4; i++)
                #pragma unroll
                for (int j = 0; j < 4; j++)
                    av[i][j] += a[i].x*b[j].x + a[i].y*b[j].y + a[i].z*b[j].z + a[i].w*b[j].w;
        }
        __syncthreads();
    }

    float (*St)[68] = reinterpret_cast<float(*)[68]>(SMEM);
    float* outs[3] = { outQ, outK, outV };
    for (int oi = 0; oi < 3; oi++) {
        __syncthreads();
        #pragma unroll
        for (int i = 0; i < 4; i++)
            #pragma unroll
            for (int j = 0; j < 4; j++)
                St[tx*4 + j][ty*4 + i] = (oi == 0) ? aq[i][j] : (oi == 1) ? ak[i][j] : av[i][j];
        __syncthreads();
        float* dst = outs[oi];
        #pragma unroll
        for (int it = 0; it < 4; it++) {
            int idx = it*256 + tid;
            int r = idx >> 4, c4 = idx & 15;
            float4 v = *reinterpret_cast<const float4*>(&St[r][c4*4]);
            *reinterpret_cast<float4*>(&dst[(size_t)(slice*64 + r)*MM + m0 + c4*4]) = v;
        }
    }
}

// ---------------- single resonance GEMM, k-split x4, transposed (O proj) ---
__global__ __launch_bounds__(256) void gemm_res(const float* __restrict__ X,
                                                const float* __restrict__ Bas,
                                                float* __restrict__ out) {
    __shared__ float SMEM[2*64*36];
    float (*As)[36] = reinterpret_cast<float(*)[36]>(SMEM);
    float (*Bs)[36] = reinterpret_cast<float(*)[36]>(SMEM + 64*36);
    int tid = threadIdx.x;
    int tx = tid & 15, ty = tid >> 4;
    int m0 = blockIdx.x * 64;
    int slice = blockIdx.y;
    int k0 = slice * 512, k1 = k0 + 512;

    float acc[4][4] = {};

    for (int kk = k0; kk < k1; kk += 32) {
        #pragma unroll
        for (int t = tid; t < 512; t += 256) {
            int r = t >> 3, c4 = t & 7;
            float4 v = *reinterpret_cast<const float4*>(&X[(size_t)(m0 + r) * DD + kk + c4 * 4]);
            As[r][c4*4+0] = v.x; As[r][c4*4+1] = v.y; As[r][c4*4+2] = v.z; As[r][c4*4+3] = v.w;
            float4 b4 = *reinterpret_cast<const float4*>(&Bas[(size_t)r * DD + kk + c4 * 4]);
            Bs[r][c4*4+0] = b4.x; Bs[r][c4*4+1] = b4.y; Bs[r][c4*4+2] = b4.z; Bs[r][c4*4+3] = b4.w;
        }
        __syncthreads();
        #pragma unroll
        for (int k = 0; k < 32; k += 4) {
            float4 a[4], b[4];
            #pragma unroll
            for (int i = 0; i < 4; i++) a[i] = *reinterpret_cast<const float4*>(&As[ty*4+i][k]);
            #pragma unroll
            for (int j = 0; j < 4; j++) b[j] = *reinterpret_cast<const float4*>(&Bs[tx*4+j][k]);
            #pragma unroll
            for (int i = 0; i < 4; i++)
                #pragma unroll
                for (int j = 0; j < 4; j++)
                    acc[i][j] += a[i].x*b[j].x + a[i].y*b[j].y + a[i].z*b[j].z + a[i].w*b[j].w;
        }
        __syncthreads();
    }

    float (*St)[68] = reinterpret_cast<float(*)[68]>(SMEM);
    __syncthreads();
    #pragma unroll
    for (int i = 0; i < 4; i++)
        #pragma unroll
        for (int j = 0; j < 4; j++)
            St[tx*4 + j][ty*4 + i] = acc[i][j];
    __syncthreads();
    #pragma unroll
    for (int it = 0; it < 4; it++) {
        int idx = it*256 + tid;
        int r = idx >> 4, c4 = idx & 15;
        float4 v = *reinterpret_cast<const float4*>(&St[r][c4*4]);
        *reinterpret_cast<float4*>(&out[(size_t)(slice*64 + r)*MM + m0 + c4*4]) = v;
    }
}

// ---------------- expand GEMMs: k-major smem, 128x128 tile, 8x8/thread -----
#define EXP_PITCH 132
#define EXP_SMEM_BYTES (2*64*EXP_PITCH*4)

__device__ __forceinline__ void exp_load_tiles(const float* __restrict__ resT,
                                               const float* __restrict__ wT,
                                               float* As, float* Bs,
                                               int m0, int n0, int tid) {
    #pragma unroll
    for (int it = 0; it < 8; it++) {
        int idx = it*256 + tid;
        int k = idx >> 5, c4 = idx & 31;
        size_t gi = (size_t)k * MM + m0 + c4*4;
        float4 v0 = *reinterpret_cast<const float4*>(&resT[gi]);
        float4 v1 = *reinterpret_cast<const float4*>(&resT[gi + (size_t)64*MM]);
        float4 v2 = *reinterpret_cast<const float4*>(&resT[gi + (size_t)128*MM]);
        float4 v3 = *reinterpret_cast<const float4*>(&resT[gi + (size_t)192*MM]);
        v0.x += v1.x + v2.x + v3.x; v0.y += v1.y + v2.y + v3.y;
        v0.z += v1.z + v2.z + v3.z; v0.w += v1.w + v2.w + v3.w;
        *reinterpret_cast<float4*>(&As[k*EXP_PITCH + c4*4]) = v0;
        float4 wv = *reinterpret_cast<const float4*>(&wT[(size_t)k*DD + n0 + c4*4]);
        *reinterpret_cast<float4*>(&Bs[k*EXP_PITCH + c4*4]) = wv;
    }
}

#define EXP_MAIN(acc) \
    _Pragma("unroll 4") \
    for (int k = 0; k < 64; k++) { \
        float4 a0 = *reinterpret_cast<float4*>(&As[k*EXP_PITCH + ty*4]); \
        float4 a1 = *reinterpret_cast<float4*>(&As[k*EXP_PITCH + 64 + ty*4]); \
        float4 b0 = *reinterpret_cast<float4*>(&Bs[k*EXP_PITCH + tx*4]); \
        float4 b1 = *reinterpret_cast<float4*>(&Bs[k*EXP_PITCH + 64 + tx*4]); \
        float am[2][4] = {{a0.x,a0.y,a0.z,a0.w},{a1.x,a1.y,a1.z,a1.w}}; \
        float bn[2][4] = {{b0.x,b0.y,b0.z,b0.w},{b1.x,b1.y,b1.z,b1.w}}; \
        _Pragma("unroll") for (int mi = 0; mi < 2; mi++) \
        _Pragma("unroll") for (int nj = 0; nj < 2; nj++) \
        _Pragma("unroll") for (int i = 0; i < 4; i++) \
        _Pragma("unroll") for (int j = 0; j < 4; j++) \
            acc[mi][nj][i][j] += am[mi][i] * bn[nj][j]; \
    }

__global__ __launch_bounds__(256) void gemm_expand(const float* __restrict__ resT,
                                                   const float* __restrict__ wT,
                                                   float* __restrict__ out) {
    extern __shared__ float es[];
    float* As = es;
    float* Bs = es + 64*EXP_PITCH;
    int tid = threadIdx.x;
    int tx = tid & 15, ty = tid >> 4;
    int m0 = blockIdx.x * 128, n0 = blockIdx.y * 128;
    exp_load_tiles(resT, wT, As, Bs, m0, n0, tid);
    __syncthreads();
    float acc[2][2][4][4] = {};
    EXP_MAIN(acc)
    #pragma unroll
    for (int mi = 0; mi < 2; mi++)
        #pragma unroll
        for (int i = 0; i < 4; i++) {
            int m = m0 + mi*64 + ty*4 + i;
            #pragma unroll
            for (int nj = 0; nj < 2; nj++) {
                float4 v = make_float4(acc[mi][nj][i][0], acc[mi][nj][i][1],
                                       acc[mi][nj][i][2], acc[mi][nj][i][3]);
                *reinterpret_cast<float4*>(&out[(size_t)m*DD + n0 + nj*64 + tx*4]) = v;
            }
        }
}

__global__ __launch_bounds__(256) void gemm_expand_qk(const float* __restrict__ resT,
                                                      const float* __restrict__ wT,
                                                      __nv_bfloat16* __restrict__ ohi,
                                                      __nv_bfloat16* __restrict__ olo) {
    extern __shared__ float es[];
    float* As = es;
    float* Bs = es + 64*EXP_PITCH;
    int tid = threadIdx.x;
    int tx = tid & 15, ty = tid >> 4;
    int m0 = blockIdx.x * 128, n0 = blockIdx.y * 128;
    exp_load_tiles(resT, wT, As, Bs, m0, n0, tid);
    __syncthreads();
    float acc[2][2][4][4] = {};
    EXP_MAIN(acc)
    #pragma unroll
    for (int mi = 0; mi < 2; mi++)
        #pragma unroll
        for (int i = 0; i < 4; i++) {
            int m = m0 + mi*64 + ty*4 + i;
            #pragma unroll
            for (int nj = 0; nj < 2; nj++) {
                int n = n0 + nj*64 + tx*4;
                uint32_t h0, l0, h1, l1;
                bf16_split2(acc[mi][nj][i][0], acc[mi][nj][i][1], h0, l0);
                bf16_split2(acc[mi][nj][i][2], acc[mi][nj][i][3], h1, l1);
                *reinterpret_cast<uint2*>(&ohi[(size_t)m*DD + n]) = make_uint2(h0, h1);
                *reinterpret_cast<uint2*>(&olo[(size_t)m*DD + n]) = make_uint2(l0, l1);
            }
        }
}

__global__ __launch_bounds__(256) void gemm_expand_vt(const float* __restrict__ resT,
                                                      const float* __restrict__ wT,
                                                      __nv_bfloat16* __restrict__ othi,
                                                      __nv_bfloat16* __restrict__ otlo) {
    extern __shared__ float es[];
    float* As = es;
    float* Bs = es + 64*EXP_PITCH;
    int tid = threadIdx.x;
    int tx = tid & 15, ty = tid >> 4;
    int m0 = blockIdx.x * 128, n0 = blockIdx.y * 128;
    exp_load_tiles(resT, wT, As, Bs, m0, n0, tid);
    __syncthreads();
    float acc[2][2][4][4] = {};
    EXP_MAIN(acc)

    float* St = es;
    int b = m0 >> 11;
    int s0 = m0 & (SS - 1);
    for (int njb = 0; njb < 2; njb++) {
        __syncthreads();
        #pragma unroll
        for (int mi = 0; mi < 2; mi++)
            #pragma unroll
            for (int j = 0; j < 4; j++) {
                float4 v = make_float4(acc[mi][njb][0][j], acc[mi][njb][1][j],
                                       acc[mi][njb][2][j], acc[mi][njb][3][j]);
                *reinterpret_cast<float4*>(&St[(tx*4 + j)*EXP_PITCH + mi*64 + ty*4]) = v;
            }
        __syncthreads();
        #pragma unroll
        for (int it = 0; it < 8; it++) {
            int idx = it*256 + tid;
            int r = idx >> 5, c4 = idx & 31;
            float4 v = *reinterpret_cast<const float4*>(&St[r*EXP_PITCH + c4*4]);
            uint32_t h0, l0, h1, l1;
            bf16_split2(v.x, v.y, h0, l0);
            bf16_split2(v.z, v.w, h1, l1);
            int ng = n0 + njb*64 + r;
            int h = ng >> 7, d = ng & 127;
            size_t base = ((size_t)(b*NH + h)*DH + d)*SS + s0 + c4*4;
            *reinterpret_cast<uint2*>(&othi[base]) = make_uint2(h0, h1);
            *reinterpret_cast<uint2*>(&otlo[base]) = make_uint2(l0, l1);
        }
    }
}

// ---- flash attention: BM=64, 2 CTAs/SM, K dbl-buf + V single-buf pipeline --
#define KP 68
#define VP 36
#define K_HALF 4352                 /* 64*KP */
#define K_BUF  8704                 /* hi+lo */
#define V_HALF 4608                 /* 128*VP */
#define OFF_V  17408                /* after 2 K bufs */
#define ATTN_SMEM_U32 (OFF_V + 2*V_HALF)   /* 26624 */
#define ATTN_SMEM_BYTES (ATTN_SMEM_U32 * 4)   /* 106496 */

__global__ __launch_bounds__(128, 2) void attn_kernel() {
    extern __shared__ uint32_t smu[];
    uint32_t sbase = (uint32_t)__cvta_generic_to_shared(smu);

    int tid = threadIdx.x;
    int wid = tid >> 5, lane = tid & 31;
    int g = lane >> 2, t4 = lane & 3;
    int qt = blockIdx.x, h = blockIdx.y, bz = blockIdx.z;
    const float scale = 0.08838834764831845f;
    int m0w = wid * 16;   // wid 0..3 -> rows 0..63

    size_t vtoff = ((size_t)(bz*NH + h) * DH) * SS;

    // ldmatrix lane->row offsets (u32 units, within tile)
    int k_lm = ((lane>>4)*8 + (lane&7)) * KP + ((lane>>3)&1)*4;
    int v_lm = ((lane>>4)*8 + (lane&7)) * VP + ((lane>>3)&1)*4;

    // ---- prologue: issue K(0) into buf 0 ----
    {
        size_t koff = (size_t)(bz*SS)*DD + h*DH;
        const uint4* kh4 = reinterpret_cast<const uint4*>(g_khi + koff);
        const uint4* kl4 = reinterpret_cast<const uint4*>(g_klo + koff);
        uint32_t kh_s = sbase, kl_s = sbase + K_HALF*4;
        for (int t = tid; t < 1024; t += 128) {
            int kr = t >> 4, kc = t & 15;
            cpa16(kh_s + (kr*KP + kc*4)*4, kh4 + (size_t)kr*256 + kc);
            cpa16(kl_s + (kr*KP + kc*4)*4, kl4 + (size_t)kr*256 + kc);
        }
        asm volatile("cp.async.commit_group;\n");
    }

    // ---- Q fragments into registers (once) ----
    size_t qrow0 = (size_t)(bz*SS + qt*64 + m0w + g)*DD + h*DH;
    const uint32_t* qh0 = reinterpret_cast<const uint32_t*>(g_qhi + qrow0);
    const uint32_t* qh8 = reinterpret_cast<const uint32_t*>(g_qhi + qrow0 + (size_t)8*DD);
    const uint32_t* ql0 = reinterpret_cast<const uint32_t*>(g_qlo + qrow0);
    const uint32_t* ql8 = reinterpret_cast<const uint32_t*>(g_qlo + qrow0 + (size_t)8*DD);
    uint32_t qa_h[8][4], qa_l[8][4];
    #pragma unroll
    for (int ks = 0; ks < 8; ks++) {
        int c = ks*8 + t4;
        qa_h[ks][0] = qh0[c];   qa_h[ks][1] = qh8[c];
        qa_h[ks][2] = qh0[c+4]; qa_h[ks][3] = qh8[c+4];
        qa_l[ks][0] = ql0[c];   qa_l[ks][1] = ql8[c];
        qa_l[ks][2] = ql0[c+4]; qa_l[ks][3] = ql8[c+4];
    }

    float4 oacc[16];
    #pragma unroll
    for (int i = 0; i < 16; i++) oacc[i] = make_float4(0.f,0.f,0.f,0.f);
    float mr0 = -INFINITY, mr1 = -INFINITY, lr0 = 0.f, lr1 = 0.f;

    for (int jt = 0; jt < 32; jt++) {
        __syncthreads();   // PV(jt-1) done: V buffer + K buf (jt+1)&1 reusable

        // ---- issue V(jt) [group] then K(jt+1) [group], fused loader ----
        {
            const uint4* vh4 = reinterpret_cast<const uint4*>(g_vthi + vtoff + jt*64);
            const uint4* vl4 = reinterpret_cast<const uint4*>(g_vtlo + vtoff + jt*64);
            uint32_t vh_s = sbase + OFF_V*4, vl_s = vh_s + V_HALF*4;
            for (int t = tid; t < 1024; t += 128) {
                int vr = t >> 3, vc = t & 7;
                cpa16(vh_s + (vr*VP + vc*4)*4, vh4 + (size_t)vr*256 + vc);
                cpa16(vl_s + (vr*VP + vc*4)*4, vl4 + (size_t)vr*256 + vc);
            }
            asm volatile("cp.async.commit_group;\n");
        }
        if (jt + 1 < 32) {
            int nb = (jt + 1) & 1;
            size_t koff = (size_t)(bz*SS + (jt+1)*64)*DD + h*DH;
            const uint4* kh4 = reinterpret_cast<const uint4*>(g_khi + koff);
            const uint4* kl4 = reinterpret_cast<const uint4*>(g_klo + koff);
            uint32_t kh_s = sbase + nb*K_BUF*4, kl_s = kh_s + K_HALF*4;
            for (int t = tid; t < 1024; t += 128) {
                int kr = t >> 4, kc = t & 15;
                cpa16(kh_s + (kr*KP + kc*4)*4, kh4 + (size_t)kr*256 + kc);
                cpa16(kl_s + (kr*KP + kc*4)*4, kl4 + (size_t)kr*256 + kc);
            }
        }
        asm volatile("cp.async.commit_group;\n");

        // ---- wait K(jt): pending {K(jt), V(jt), K(jt+1)} -> keep newest 2 ----
        asm volatile("cp.async.wait_group 2;\n" ::: "memory");
        __syncthreads();

        int buf = jt & 1;
        uint32_t kh_base = sbase + (buf*K_BUF + k_lm)*4;
        uint32_t kl_base = kh_base + K_HALF*4;

        // ---- S = Q @ K^T ----
        float4 sc[8];
        #pragma unroll
        for (int i = 0; i < 8; i++) sc[i] = make_float4(0.f,0.f,0.f,0.f);
        #pragma unroll
        for (int ks = 0; ks < 8; ks++) {
            #pragma unroll
            for (int nb = 0; nb < 8; nb += 2) {
                uint32_t h0, h1, h2, h3, l0, l1, l2, l3;
                ldsm_x4(h0, h1, h2, h3, kh_base + (nb*8*KP + ks*8)*4);
                ldsm_x4(l0, l1, l2, l3, kl_base + (nb*8*KP + ks*8)*4);
                mma_bf16(sc[nb],   qa_h[ks], h0, h1);
                mma_bf16(sc[nb],   qa_h[ks], l0, l1);
                mma_bf16(sc[nb],   qa_l[ks], h0, h1);
                mma_bf16(sc[nb+1], qa_h[ks], h2, h3);
                mma_bf16(sc[nb+1], qa_h[ks], l2, l3);
                mma_bf16(sc[nb+1], qa_l[ks], h2, h3);
            }
        }

        // ---- online softmax + P splits (V-independent) BEFORE the V wait ----
        float mx0 = -INFINITY, mx1 = -INFINITY;
        #pragma unroll
        for (int nt = 0; nt < 8; nt++) {
            mx0 = fmaxf(mx0, fmaxf(sc[nt].x, sc[nt].y));
            mx1 = fmaxf(mx1, fmaxf(sc[nt].z, sc[nt].w));
        }
        mx0 *= scale; mx1 *= scale;
        mx0 = fmaxf(mx0, __shfl_xor_sync(0xffffffffu, mx0, 1));
        mx0 = fmaxf(mx0, __shfl_xor_sync(0xffffffffu, mx0, 2));
        mx1 = fmaxf(mx1, __shfl_xor_sync(0xffffffffu, mx1, 1));
        mx1 = fmaxf(mx1, __shfl_xor_sync(0xffffffffu, mx1, 2));
        float mn0 = fmaxf(mr0, mx0), mn1 = fmaxf(mr1, mx1);
        float ps0 = 0.f, ps1 = 0.f;
        #pragma unroll
        for (int nt = 0; nt < 8; nt++) {
            sc[nt].x = __expf(sc[nt].x*scale - mn0);
            sc[nt].y = __expf(sc[nt].y*scale - mn0);
            sc[nt].z = __expf(sc[nt].z*scale - mn1);
            sc[nt].w = __expf(sc[nt].w*scale - mn1);
            ps0 += sc[nt].x + sc[nt].y;
            ps1 += sc[nt].z + sc[nt].w;
        }
        ps0 += __shfl_xor_sync(0xffffffffu, ps0, 1);
        ps0 += __shfl_xor_sync(0xffffffffu, ps0, 2);
        ps1 += __shfl_xor_sync(0xffffffffu, ps1, 1);
        ps1 += __shfl_xor_sync(0xffffffffu, ps1, 2);
        float al0 = __expf(mr0 - mn0), al1 = __expf(mr1 - mn1);
        lr0 = lr0*al0 + ps0; lr1 = lr1*al1 + ps1;
        mr0 = mn0; mr1 = mn1;
        #pragma unroll
        for (int i = 0; i < 16; i++) {
            oacc[i].x *= al0; oacc[i].y *= al0;
            oacc[i].z *= al1; oacc[i].w *= al1;
        }
        // P A-fragments from sc registers (still V-independent)
        uint32_t pah[4][4], pal[4][4];
        #pragma unroll
        for (int ks = 0; ks < 4; ks++) {
            bf16_split2(sc[2*ks].x,   sc[2*ks].y,   pah[ks][0], pal[ks][0]);
            bf16_split2(sc[2*ks].z,   sc[2*ks].w,   pah[ks][1], pal[ks][1]);
            bf16_split2(sc[2*ks+1].x, sc[2*ks+1].y, pah[ks][2], pal[ks][2]);
            bf16_split2(sc[2*ks+1].z, sc[2*ks+1].w, pah[ks][3], pal[ks][3]);
        }

        // ---- wait V(jt): pending {V(jt), K(jt+1)} -> keep newest 1 ----
        asm volatile("cp.async.wait_group 1;\n" ::: "memory");
        __syncthreads();

        uint32_t vh_base = sbase + (OFF_V + v_lm)*4;
        uint32_t vl_base = vh_base + V_HALF*4;

        // ---- O += P @ V ----
        #pragma unroll
        for (int ks = 0; ks < 4; ks++) {
            #pragma unroll
            for (int nb = 0; nb < 16; nb += 2) {
                uint32_t h0, h1, h2, h3, l0, l1, l2, l3;
                ldsm_x4(h0, h1, h2, h3, vh_base + (nb*8*VP + ks*8)*4);
                ldsm_x4(l0, l1, l2, l3, vl_base + (nb*8*VP + ks*8)*4);
                mma_bf16(oacc[nb],   pah[ks], h0, h1);
                mma_bf16(oacc[nb],   pah[ks], l0, l1);
                mma_bf16(oacc[nb],   pal[ks], h0, h1);
                mma_bf16(oacc[nb+1], pah[ks], h2, h3);
                mma_bf16(oacc[nb+1], pah[ks], l2, l3);
                mma_bf16(oacc[nb+1], pal[ks], h2, h3);
            }
        }
    }

    // ---- epilogue ----
    float inv0 = 1.f/lr0, inv1 = 1.f/lr1;
    size_t row0 = (size_t)(bz*SS + qt*64 + m0w + g);
    float* ob0 = g_ao + row0*DD + h*DH;
    float* ob1 = ob0 + (size_t)8*DD;
    #pragma unroll
    for (int nt = 0; nt < 16; nt++) {
        int c = nt*8 + 2*t4;
        *reinterpret_cast<float2*>(&ob0[c]) = make_float2(oacc[nt].x*inv0, oacc[nt].y*inv0);
        *reinterpret_cast<float2*>(&ob1[c]) = make_float2(oacc[nt].z*inv1, oacc[nt].w*inv1);
    }
}

// ---------------- launch ----------------
extern "C" void kernel_launch(void* const* d_in, const int* in_sizes, int n_in,
                              void* d_out, int out_size) {
    const float* x       = (const float*)d_in[0];
    const float* basis_q = (const float*)d_in[1];
    const float* phase_q = (const float*)d_in[2];
    const float* amp_q   = (const float*)d_in[3];
    const float* basis_k = (const float*)d_in[4];
    const float* phase_k = (const float*)d_in[5];
    const float* amp_k   = (const float*)d_in[6];
    const float* basis_v = (const float*)d_in[7];
    const float* phase_v = (const float*)d_in[8];
    const float* amp_v   = (const float*)d_in[9];
    const float* basis_o = (const float*)d_in[10];
    const float* phase_o = (const float*)d_in[11];
    const float* amp_o   = (const float*)d_in[12];
    float* out = (float*)d_out;

    float *wq, *wk, *wv, *wo, *resq, *resk, *resv, *ao;
    __nv_bfloat16 *qhi, *qlo, *khi, *klo, *vthi, *vtlo;
    cudaGetSymbolAddress((void**)&wq, g_wq);
    cudaGetSymbolAddress((void**)&wk, g_wk);
    cudaGetSymbolAddress((void**)&wv, g_wv);
    cudaGetSymbolAddress((void**)&wo, g_wo);
    cudaGetSymbolAddress((void**)&resq, g_resq);
    cudaGetSymbolAddress((void**)&resk, g_resk);
    cudaGetSymbolAddress((void**)&resv, g_resv);
    cudaGetSymbolAddress((void**)&ao, g_ao);
    cudaGetSymbolAddress((void**)&qhi, g_qhi);
    cudaGetSymbolAddress((void**)&qlo, g_qlo);
    cudaGetSymbolAddress((void**)&khi, g_khi);
    cudaGetSymbolAddress((void**)&klo, g_klo);
    cudaGetSymbolAddress((void**)&vthi, g_vthi);
    cudaGetSymbolAddress((void**)&vtlo, g_vtlo);

    cudaFuncSetAttribute(attn_kernel, cudaFuncAttributeMaxDynamicSharedMemorySize,
                         ATTN_SMEM_BYTES);
    cudaFuncSetAttribute(gemm_expand, cudaFuncAttributeMaxDynamicSharedMemorySize,
                         EXP_SMEM_BYTES);
    cudaFuncSetAttribute(gemm_expand_qk, cudaFuncAttributeMaxDynamicSharedMemorySize,
                         EXP_SMEM_BYTES);
    cudaFuncSetAttribute(gemm_expand_vt, cudaFuncAttributeMaxDynamicSharedMemorySize,
                         EXP_SMEM_BYTES);

    wcos_t<<<dim3(32, 4), 256>>>(amp_q, phase_q, wq, amp_k, phase_k, wk,
                                 amp_v, phase_v, wv, amp_o, phase_o, wo);

    gemm_res_qkv<<<dim3(64, 4), 256>>>(x, basis_q, basis_k, basis_v, resq, resk, resv);
    gemm_expand_qk<<<dim3(32, 16), 256, EXP_SMEM_BYTES>>>(resq, wq, qhi, qlo);
    gemm_expand_qk<<<dim3(32, 16), 256, EXP_SMEM_BYTES>>>(resk, wk, khi, klo);
    gemm_expand_vt<<<dim3(32, 16), 256, EXP_SMEM_BYTES>>>(resv, wv, vthi, vtlo);

    // BM=64: 32 q-tiles, 128 threads, 2 CTAs/SM
    attn_kernel<<<dim3(32, NH, BB), 128, ATTN_SMEM_BYTES>>>();

    gemm_res<<<dim3(64, 4), 256>>>(ao, basis_o, resq);
    gemm_expand<<<dim3(32, 16), 256, EXP_SMEM_BYTES>>>(resq, wo, out);
}